// round 10
// baseline (speedup 1.0000x reference)
#include <cuda_runtime.h>

// Batched 11-qubit PQC — transfer-matrix form, two-kernel split:
//   K1: build folded tables for every batch element -> global scratch (L2).
//   K2: one CTA per batch element streams the 2048 outputs from tables.
//
//   out[w] = Re( V0(c0)·M1(c1)···M9(c9)·G(c10) ),  c = graymap(w)
//   T1[c0..c3] = V0·M1·M2·M3            (16 row 2-vectors)
//   T2[c4..c7] = M4·M5·M6·M7            (16 2x2 matrices)
//   W[c8..c10] = M8·M9·G                (8 col 2-vectors)
// Scratch row per batch (56 float4): [0..15]=T1, [16..47]=T2 (row pairs), [48..55]=W.

#define NQ       11
#define NL       2
#define SDIM     2048
#define NTHREADS 256
#define NB       8              // batches per build-CTA
#define MAXB     4096
#define TROW     56             // float4 per batch table row

__device__ float4 g_tab[MAXB * TROW];   // 3.67 MB scratch (static: no alloc)

struct C2 { float r, i; };
__device__ __forceinline__ C2 cmul(C2 a, C2 b) {
    return { a.r*b.r - a.i*b.i, a.r*b.i + a.i*b.r };
}
__device__ __forceinline__ C2 cfma(C2 a, C2 b, C2 c) {   // a*b + c
    return { fmaf(a.r, b.r, fmaf(-a.i, b.i, c.r)),
             fmaf(a.r, b.i, fmaf( a.i, b.r, c.i)) };
}

// ---------------------------------------------------------------- kernel 1
__global__ __launch_bounds__(NTHREADS)
void pqc_build(const float* __restrict__ theta,
               const int*   __restrict__ positions,
               int batch)
{
    __shared__ float U1[NB][NQ][8];
    __shared__ float U2[NB][NQ][8];
    __shared__ float V01[NB][4][4];
    __shared__ float P23[NB][4][8];
    __shared__ float P45[NB][4][8];
    __shared__ float P67[NB][4][8];
    __shared__ float P910[NB][4][4];

    const int t  = threadIdx.x;
    const int b0 = blockIdx.x * NB;

    // ---- Stage A: gate matrices U = Rz(g)*Ry(b)*Rx(a), half-angles ----
    if (t < NB * NL * NQ) {              // 176 threads
        const int j = t / (NL * NQ);
        const int g = t - j * (NL * NQ);
        const int l = (g >= NQ) ? 1 : 0;
        const int q = g - l * NQ;
        const int bidx = min(b0 + j, batch - 1);
        const int p = positions[bidx];
        const float* th = theta + (long long)p * (NL * 3 * NQ) + l * 3 * NQ + q * 3;
        const float a  = 0.5f * th[0];
        const float bb = 0.5f * th[1];
        const float gg = 0.5f * th[2];
        float sa, ca, sb, cb, sg, cg;
        sincosf(a,  &sa, &ca);
        sincosf(bb, &sb, &cb);
        sincosf(gg, &sg, &cg);
        const float cbca = cb * ca, sbsa = sb * sa;
        const float sbca = sb * ca, cbsa = cb * sa;
        float* U = l ? U2[j][q] : U1[j][q];
        U[0] =  cg * cbca + sg * sbsa;   // u00.re
        U[1] =  cg * sbsa - sg * cbca;   // u00.im
        U[2] = -cg * sbca - sg * cbsa;   // u01.re
        U[3] = -cg * cbsa + sg * sbca;   // u01.im
        U[4] =  cg * sbca + sg * cbsa;   // u10.re
        U[5] =  sg * sbca - cg * cbsa;   // u10.im
        U[6] =  cg * cbca + sg * sbsa;   // u11.re
        U[7] =  sg * cbca - cg * sbsa;   // u11.im
    }
    __syncthreads();

    #define BUILD_M(m, U1q, U2q, c)                            \
        {                                                      \
            const C2 u0 = { (U2q)[(c)*4+0], (U2q)[(c)*4+1] };  \
            const C2 u1 = { (U2q)[(c)*4+2], (U2q)[(c)*4+3] };  \
            const C2 f0 = { (U1q)[0], (U1q)[1] };              \
            const C2 f1 = { (U1q)[4], (U1q)[5] };              \
            m[0] = cmul(u0, f0);                               \
            m[1] = cmul(u1, f1);                               \
            m[2] = cmul(u0, f1);                               \
            m[3] = cmul(u1, f0);                               \
        }

    // ---- Stage B1: pair products (8 x 20 = 160 threads) ----
    if (t < NB * 20) {
        const int j = t / 20;
        const int i = t - j * 20;
        if (i < 4) {                     // V01 = V0(c0)·M1(c1)
            const int c0 = i & 1, c1 = i >> 1;
            const C2 u0 = { U2[j][0][c0*4+0], U2[j][0][c0*4+1] };
            const C2 u1 = { U2[j][0][c0*4+2], U2[j][0][c0*4+3] };
            const C2 f0 = { U1[j][0][0], U1[j][0][1] };
            const C2 f1 = { U1[j][0][4], U1[j][0][5] };
            const C2 v0 = cmul(u0, f0);
            const C2 v1 = cmul(u1, f1);
            C2 m[4]; BUILD_M(m, U1[j][1], U2[j][1], c1);
            const C2 r0 = cfma(v0, m[0], cmul(v1, m[2]));
            const C2 r1 = cfma(v0, m[1], cmul(v1, m[3]));
            V01[j][i][0] = r0.r; V01[j][i][1] = r0.i;
            V01[j][i][2] = r1.r; V01[j][i][3] = r1.i;
        } else if (i < 16) {             // P23 / P45 / P67
            const int grp = (i - 4) >> 2;
            const int idx = (i - 4) & 3;
            const int qa = 2 + grp * 2, qb = qa + 1;
            const int ca = idx & 1, cb = idx >> 1;
            C2 A[4], B[4];
            BUILD_M(A, U1[j][qa], U2[j][qa], ca);
            BUILD_M(B, U1[j][qb], U2[j][qb], cb);
            float* o = (grp == 0) ? P23[j][idx] : (grp == 1) ? P45[j][idx] : P67[j][idx];
            const C2 c00 = cfma(A[0], B[0], cmul(A[1], B[2]));
            const C2 c01 = cfma(A[0], B[1], cmul(A[1], B[3]));
            const C2 c10 = cfma(A[2], B[0], cmul(A[3], B[2]));
            const C2 c11 = cfma(A[2], B[1], cmul(A[3], B[3]));
            o[0] = c00.r; o[1] = c00.i; o[2] = c01.r; o[3] = c01.i;
            o[4] = c10.r; o[5] = c10.i; o[6] = c11.r; o[7] = c11.i;
        } else {                         // P910 = M9(c9)·G(c10)
            const int idx = i - 16;
            const int c9 = idx & 1, c10 = idx >> 1;
            const C2 u0 = { U2[j][10][c10*4+0], U2[j][10][c10*4+1] };
            const C2 u1 = { U2[j][10][c10*4+2], U2[j][10][c10*4+3] };
            const C2 f0 = { U1[j][10][0], U1[j][10][1] };
            const C2 f1 = { U1[j][10][4], U1[j][10][5] };
            const C2 g0 = cfma(u0, f0, cmul(u1, f1));
            const C2 g1 = cfma(u0, f1, cmul(u1, f0));
            C2 m[4]; BUILD_M(m, U1[j][9], U2[j][9], c9);
            const C2 p0 = cfma(m[0], g0, cmul(m[1], g1));
            const C2 p1 = cfma(m[2], g0, cmul(m[3], g1));
            P910[j][idx][0] = p0.r; P910[j][idx][1] = p0.i;
            P910[j][idx][2] = p1.r; P910[j][idx][3] = p1.i;
        }
    }
    __syncthreads();

    // ---- Stage B2: group products -> global scratch (direct STG.128) ----
    {
        const int j = t >> 5;
        const int i = t & 31;
        const int b = b0 + j;
        if (b < batch) {
            float4* row = g_tab + (long long)b * TROW;
            if (i < 16) {                // T1[i] = V01[i&3] · P23[i>>2]
                const float* a  = V01[j][i & 3];
                const float* Bm = P23[j][i >> 2];
                const C2 a0 = { a[0], a[1] }, a1 = { a[2], a[3] };
                const C2 B00 = { Bm[0], Bm[1] }, B01 = { Bm[2], Bm[3] };
                const C2 B10 = { Bm[4], Bm[5] }, B11 = { Bm[6], Bm[7] };
                const C2 r0 = cfma(a0, B00, cmul(a1, B10));
                const C2 r1 = cfma(a0, B01, cmul(a1, B11));
                row[i] = make_float4(r0.r, r0.i, r1.r, r1.i);
            } else {                     // T2[ii] = P45 · P67 (two rows)
                const int ii = i - 16;
                const float* Am = P45[j][ii & 3];
                const float* Bm = P67[j][ii >> 2];
                const C2 A00 = { Am[0], Am[1] }, A01 = { Am[2], Am[3] };
                const C2 A10 = { Am[4], Am[5] }, A11 = { Am[6], Am[7] };
                const C2 B00 = { Bm[0], Bm[1] }, B01 = { Bm[2], Bm[3] };
                const C2 B10 = { Bm[4], Bm[5] }, B11 = { Bm[6], Bm[7] };
                const C2 c00 = cfma(A00, B00, cmul(A01, B10));
                const C2 c01 = cfma(A00, B01, cmul(A01, B11));
                const C2 c10 = cfma(A10, B00, cmul(A11, B10));
                const C2 c11 = cfma(A10, B01, cmul(A11, B11));
                row[16 + 2*ii]     = make_float4(c00.r, c00.i, c01.r, c01.i);
                row[16 + 2*ii + 1] = make_float4(c10.r, c10.i, c11.r, c11.i);
            }
        }
    }
    if (t < NB * 8) {                    // W[i] = M8(c8) · P910
        const int j = t >> 3;
        const int i = t & 7;
        const int b = b0 + j;
        if (b < batch) {
            const int c8 = i & 1;
            const float* pv = P910[j][i >> 1];
            const C2 p0 = { pv[0], pv[1] }, p1 = { pv[2], pv[3] };
            C2 m[4]; BUILD_M(m, U1[j][8], U2[j][8], c8);
            const C2 w0 = cfma(m[0], p0, cmul(m[1], p1));
            const C2 w1 = cfma(m[2], p0, cmul(m[3], p1));
            g_tab[(long long)b * TROW + 48 + i] = make_float4(w0.r, w0.i, w1.r, w1.i);
        }
    }
    #undef BUILD_M
}

// ---------------------------------------------------------------- kernel 2
__global__ __launch_bounds__(NTHREADS)
void pqc_main(float* __restrict__ out)
{
    __shared__ float4 s[TROW];

    const int b = blockIdx.x;
    const int t = threadIdx.x;

    if (t < TROW)
        s[t] = g_tab[(long long)b * TROW + t];
    __syncthreads();

    const int c  = (t ^ (t << 1)) & 255;   // graymap bits 0..7
    const int t7 = (t >> 7) & 1;

    const float4 a  = s[c & 15];
    const float4 B0 = s[16 + 2*(c >> 4)];
    const float4 B1 = s[16 + 2*(c >> 4) + 1];
    const C2 a0 = { a.x, a.y }, a1 = { a.z, a.w };
    const C2 v20 = cfma(a0, { B0.x, B0.y }, cmul(a1, { B1.x, B1.y }));
    const C2 v21 = cfma(a0, { B0.z, B0.w }, cmul(a1, { B1.z, B1.w }));

    float* ob = out + (long long)b * SDIM + t;
    #pragma unroll
    for (int k = 0; k < 8; ++k) {
        const int cc = (((k ^ (k << 1)) & 7) ^ t7);   // warp-uniform
        const float4 w = s[48 + cc];
        const float val = v20.r*w.x - v20.i*w.y + v21.r*w.z - v21.i*w.w;
        ob[k << 8] = val;
    }
}

extern "C" void kernel_launch(void* const* d_in, const int* in_sizes, int n_in,
                              void* d_out, int out_size)
{
    const float* theta     = (const float*)d_in[0];
    const int*   positions = (const int*)d_in[1];
    float*       out       = (float*)d_out;

    const int batch = in_sizes[1];                  // 4096
    const int bblk  = (batch + NB - 1) / NB;        // 512
    pqc_build<<<bblk, NTHREADS>>>(theta, positions, batch);
    pqc_main<<<batch, NTHREADS>>>(out);
}

// round 11
// speedup vs baseline: 1.1544x; 1.1544x over previous
#include <cuda_runtime.h>

// Batched 11-qubit PQC — transfer-matrix form, fused single kernel.
// NB=4 batches per CTA (grid 1024 -> ~7 CTAs/SM), 2-barrier setup where
// every folded table entry is chained directly from the gate matrices.
//
//   out[w] = Re( V0(c0)·M1(c1)···M9(c9)·G(c10) ),  c = graymap(w)
//   T1[c0..c3] = V0·M1·M2·M3            (16 row 2-vectors)
//   T2[c4..c7] = M4·M5·M6·M7            (16 2x2 matrices, 2 rows each)
//   W [c8..c10]= M8·M9·G                (8 col 2-vectors)
// Table row (56 float4): [0..15]=T1, [16..47]=T2 row pairs, [48..55]=W.

#define NQ       11
#define NL       2
#define SDIM     2048
#define NTHREADS 256
#define NB       4              // batches per CTA
#define TROW     56

struct C2 { float r, i; };
__device__ __forceinline__ C2 cmul(C2 a, C2 b) {
    return { a.r*b.r - a.i*b.i, a.r*b.i + a.i*b.r };
}
__device__ __forceinline__ C2 cfma(C2 a, C2 b, C2 c) {   // a*b + c
    return { fmaf(a.r, b.r, fmaf(-a.i, b.i, c.r)),
             fmaf(a.r, b.i, fmaf( a.i, b.r, c.i)) };
}

// M_q(c)[zp][zq] = U2_q[c,zq] * f_q(zq^zp);  f_q from column 0 of U1_q.
// Layout: m[0]=M00, m[1]=M01, m[2]=M10, m[3]=M11.
__device__ __forceinline__ void build_m(C2 m[4], const float* U1q,
                                        const float* U2q, int c) {
    const C2 u0 = { U2q[c*4+0], U2q[c*4+1] };
    const C2 u1 = { U2q[c*4+2], U2q[c*4+3] };
    const C2 f0 = { U1q[0], U1q[1] };
    const C2 f1 = { U1q[4], U1q[5] };
    m[0] = cmul(u0, f0);   // zp0,zq0
    m[1] = cmul(u1, f1);   // zp0,zq1
    m[2] = cmul(u0, f1);   // zp1,zq0
    m[3] = cmul(u1, f0);   // zp1,zq1
}

__global__ __launch_bounds__(NTHREADS)
void pqc_kernel(const float* __restrict__ theta,
                const int*   __restrict__ positions,
                float*       __restrict__ out,
                int batch)
{
    __shared__ float  U1[NB][NQ][8];     // layer-1 gates
    __shared__ float  U2[NB][NQ][8];     // layer-2 gates
    __shared__ float4 Ts[NB][TROW];      // folded tables

    const int t  = threadIdx.x;
    const int b0 = blockIdx.x * NB;

    // ---- Stage A: gate matrices U = Rz(g)*Ry(b)*Rx(a), half-angles ----
    if (t < NB * NL * NQ) {              // 88 threads
        const int j = t / (NL * NQ);
        const int g = t - j * (NL * NQ);
        const int l = (g >= NQ) ? 1 : 0;
        const int q = g - l * NQ;
        const int bidx = min(b0 + j, batch - 1);
        const int p = positions[bidx];
        const float* th = theta + (long long)p * (NL * 3 * NQ) + l * 3 * NQ + q * 3;
        const float a  = 0.5f * th[0];
        const float bb = 0.5f * th[1];
        const float gg = 0.5f * th[2];
        float sa, ca, sb, cb, sg, cg;
        sincosf(a,  &sa, &ca);
        sincosf(bb, &sb, &cb);
        sincosf(gg, &sg, &cg);
        const float cbca = cb * ca, sbsa = sb * sa;
        const float sbca = sb * ca, cbsa = cb * sa;
        float* U = l ? U2[j][q] : U1[j][q];
        U[0] =  cg * cbca + sg * sbsa;   // u00.re
        U[1] =  cg * sbsa - sg * cbca;   // u00.im
        U[2] = -cg * sbca - sg * cbsa;   // u01.re
        U[3] = -cg * cbsa + sg * sbca;   // u01.im
        U[4] =  cg * sbca + sg * cbsa;   // u10.re
        U[5] =  sg * sbca - cg * cbsa;   // u10.im
        U[6] =  cg * cbca + sg * sbsa;   // u11.re
        U[7] =  sg * cbca - cg * sbsa;   // u11.im
    }
    __syncthreads();

    // ---- Stage B: fold tables by direct chains (40 items per batch) ----
    {
        const int j = t >> 6;            // 64-thread group per batch
        const int i = t & 63;
        if (i < 16) {
            // T1[i] = V0(i0)·M1(i1)·M2(i2)·M3(i3)   (row 2-vector chain)
            const int c0 = i & 1;
            const C2 u0 = { U2[j][0][c0*4+0], U2[j][0][c0*4+1] };
            const C2 u1 = { U2[j][0][c0*4+2], U2[j][0][c0*4+3] };
            const C2 f0 = { U1[j][0][0], U1[j][0][1] };
            const C2 f1 = { U1[j][0][4], U1[j][0][5] };
            C2 v0 = cmul(u0, f0);
            C2 v1 = cmul(u1, f1);
            #pragma unroll
            for (int q = 1; q <= 3; ++q) {
                C2 m[4]; build_m(m, U1[j][q], U2[j][q], (i >> q) & 1);
                const C2 n0 = cfma(v0, m[0], cmul(v1, m[2]));
                const C2 n1 = cfma(v0, m[1], cmul(v1, m[3]));
                v0 = n0; v1 = n1;
            }
            Ts[j][i] = make_float4(v0.r, v0.i, v1.r, v1.i);
        } else if (i < 32) {
            // T2[ii] = M4·M5·M6·M7  (2x2 chain)
            const int ii = i - 16;
            C2 A[4]; build_m(A, U1[j][4], U2[j][4], ii & 1);
            #pragma unroll
            for (int q = 5; q <= 7; ++q) {
                C2 B[4]; build_m(B, U1[j][q], U2[j][q], (ii >> (q - 4)) & 1);
                const C2 c00 = cfma(A[0], B[0], cmul(A[1], B[2]));
                const C2 c01 = cfma(A[0], B[1], cmul(A[1], B[3]));
                const C2 c10 = cfma(A[2], B[0], cmul(A[3], B[2]));
                const C2 c11 = cfma(A[2], B[1], cmul(A[3], B[3]));
                A[0] = c00; A[1] = c01; A[2] = c10; A[3] = c11;
            }
            Ts[j][16 + 2*ii]     = make_float4(A[0].r, A[0].i, A[1].r, A[1].i);
            Ts[j][16 + 2*ii + 1] = make_float4(A[2].r, A[2].i, A[3].r, A[3].i);
        } else if (i < 40) {
            // W[iw] = M8(c8)·M9(c9)·G(c10)   (col 2-vector chain)
            const int iw  = i - 32;
            const int c8  = iw & 1;
            const int c9  = (iw >> 1) & 1;
            const int c10 = iw >> 2;
            const C2 u0 = { U2[j][10][c10*4+0], U2[j][10][c10*4+1] };
            const C2 u1 = { U2[j][10][c10*4+2], U2[j][10][c10*4+3] };
            const C2 f0 = { U1[j][10][0], U1[j][10][1] };
            const C2 f1 = { U1[j][10][4], U1[j][10][5] };
            C2 g0 = cfma(u0, f0, cmul(u1, f1));   // G[zp=0]
            C2 g1 = cfma(u0, f1, cmul(u1, f0));   // G[zp=1]
            {
                C2 m[4]; build_m(m, U1[j][9], U2[j][9], c9);
                const C2 n0 = cfma(m[0], g0, cmul(m[1], g1));
                const C2 n1 = cfma(m[2], g0, cmul(m[3], g1));
                g0 = n0; g1 = n1;
            }
            {
                C2 m[4]; build_m(m, U1[j][8], U2[j][8], c8);
                const C2 n0 = cfma(m[0], g0, cmul(m[1], g1));
                const C2 n1 = cfma(m[2], g0, cmul(m[3], g1));
                g0 = n0; g1 = n1;
            }
            Ts[j][48 + iw] = make_float4(g0.r, g0.i, g1.r, g1.i);
        }
    }
    __syncthreads();

    // ---- Main: per-thread fold + 8 leaves, for each of the NB batches ----
    const int c  = (t ^ (t << 1)) & 255;   // graymap bits 0..7
    const int t7 = (t >> 7) & 1;

    #pragma unroll
    for (int j = 0; j < NB; ++j) {
        if (b0 + j >= batch) break;
        const float4 a  = Ts[j][c & 15];
        const float4 B0 = Ts[j][16 + 2*(c >> 4)];
        const float4 B1 = Ts[j][16 + 2*(c >> 4) + 1];
        const C2 a0 = { a.x, a.y }, a1 = { a.z, a.w };
        const C2 v20 = cfma(a0, { B0.x, B0.y }, cmul(a1, { B1.x, B1.y }));
        const C2 v21 = cfma(a0, { B0.z, B0.w }, cmul(a1, { B1.z, B1.w }));

        float* ob = out + (long long)(b0 + j) * SDIM + t;
        #pragma unroll
        for (int k = 0; k < 8; ++k) {
            const int cc = (((k ^ (k << 1)) & 7) ^ t7);   // warp-uniform
            const float4 w = Ts[j][48 + cc];
            const float val = v20.r*w.x - v20.i*w.y + v21.r*w.z - v21.i*w.w;
            ob[k << 8] = val;
        }
    }
}

extern "C" void kernel_launch(void* const* d_in, const int* in_sizes, int n_in,
                              void* d_out, int out_size)
{
    const float* theta     = (const float*)d_in[0];
    const int*   positions = (const int*)d_in[1];
    float*       out       = (float*)d_out;

    const int batch  = in_sizes[1];                 // 4096
    const int blocks = (batch + NB - 1) / NB;       // 1024
    pqc_kernel<<<blocks, NTHREADS>>>(theta, positions, out, batch);
}

// round 12
// speedup vs baseline: 1.3772x; 1.1930x over previous
#include <cuda_runtime.h>

// Batched 11-qubit PQC — transfer-matrix form, fused single kernel.
// NB=4 batches per CTA, grid 1024; __launch_bounds__(256,7) pins 7 CTAs/SM
// so the whole grid runs in ONE wave. __sincosf (MUFU) for gate angles.
//
//   out[w] = Re( V0(c0)·M1(c1)···M9(c9)·G(c10) ),  c = graymap(w)
//   T1[c0..c3] = V0·M1·M2·M3            (16 row 2-vectors)
//   T2[c4..c7] = M4·M5·M6·M7            (16 2x2 matrices, 2 rows each)
//   W [c8..c10]= M8·M9·G                (8 col 2-vectors)
// Table row (56 float4): [0..15]=T1, [16..47]=T2 row pairs, [48..55]=W.

#define NQ       11
#define NL       2
#define SDIM     2048
#define NTHREADS 256
#define NB       4              // batches per CTA
#define TROW     56

struct C2 { float r, i; };
__device__ __forceinline__ C2 cmul(C2 a, C2 b) {
    return { a.r*b.r - a.i*b.i, a.r*b.i + a.i*b.r };
}
__device__ __forceinline__ C2 cfma(C2 a, C2 b, C2 c) {   // a*b + c
    return { fmaf(a.r, b.r, fmaf(-a.i, b.i, c.r)),
             fmaf(a.r, b.i, fmaf( a.i, b.r, c.i)) };
}

// M_q(c)[zp][zq] = U2_q[c,zq] * f_q(zq^zp);  f_q from column 0 of U1_q.
__device__ __forceinline__ void build_m(C2 m[4], const float* U1q,
                                        const float* U2q, int c) {
    const C2 u0 = { U2q[c*4+0], U2q[c*4+1] };
    const C2 u1 = { U2q[c*4+2], U2q[c*4+3] };
    const C2 f0 = { U1q[0], U1q[1] };
    const C2 f1 = { U1q[4], U1q[5] };
    m[0] = cmul(u0, f0);   // zp0,zq0
    m[1] = cmul(u1, f1);   // zp0,zq1
    m[2] = cmul(u0, f1);   // zp1,zq0
    m[3] = cmul(u1, f0);   // zp1,zq1
}

__global__ __launch_bounds__(NTHREADS, 7)
void pqc_kernel(const float* __restrict__ theta,
                const int*   __restrict__ positions,
                float*       __restrict__ out,
                int batch)
{
    __shared__ float  U1[NB][NQ][8];     // layer-1 gates
    __shared__ float  U2[NB][NQ][8];     // layer-2 gates
    __shared__ float4 Ts[NB][TROW];      // folded tables

    const int t  = threadIdx.x;
    const int b0 = blockIdx.x * NB;

    // ---- Stage A: gate matrices U = Rz(g)*Ry(b)*Rx(a), half-angles ----
    if (t < NB * NL * NQ) {              // 88 threads
        const int j = t / (NL * NQ);
        const int g = t - j * (NL * NQ);
        const int l = (g >= NQ) ? 1 : 0;
        const int q = g - l * NQ;
        const int bidx = min(b0 + j, batch - 1);
        const int p = positions[bidx];
        const float* th = theta + (long long)p * (NL * 3 * NQ) + l * 3 * NQ + q * 3;
        const float a  = 0.5f * th[0];
        const float bb = 0.5f * th[1];
        const float gg = 0.5f * th[2];
        float sa, ca, sb, cb, sg, cg;
        __sincosf(a,  &sa, &ca);         // MUFU fast path: |ang| ~ 0.05,
        __sincosf(bb, &sb, &cb);         // error ~2^-21 << 1e-3 tolerance
        __sincosf(gg, &sg, &cg);
        const float cbca = cb * ca, sbsa = sb * sa;
        const float sbca = sb * ca, cbsa = cb * sa;
        float* U = l ? U2[j][q] : U1[j][q];
        U[0] =  cg * cbca + sg * sbsa;   // u00.re
        U[1] =  cg * sbsa - sg * cbca;   // u00.im
        U[2] = -cg * sbca - sg * cbsa;   // u01.re
        U[3] = -cg * cbsa + sg * sbca;   // u01.im
        U[4] =  cg * sbca + sg * cbsa;   // u10.re
        U[5] =  sg * sbca - cg * cbsa;   // u10.im
        U[6] =  cg * cbca + sg * sbsa;   // u11.re
        U[7] =  sg * cbca - cg * sbsa;   // u11.im
    }
    __syncthreads();

    // ---- Stage B: fold tables by direct chains (40 items per batch) ----
    {
        const int j = t >> 6;            // 64-thread group per batch
        const int i = t & 63;
        if (i < 16) {
            // T1[i] = V0(i0)·M1(i1)·M2(i2)·M3(i3)   (row 2-vector chain)
            const int c0 = i & 1;
            const C2 u0 = { U2[j][0][c0*4+0], U2[j][0][c0*4+1] };
            const C2 u1 = { U2[j][0][c0*4+2], U2[j][0][c0*4+3] };
            const C2 f0 = { U1[j][0][0], U1[j][0][1] };
            const C2 f1 = { U1[j][0][4], U1[j][0][5] };
            C2 v0 = cmul(u0, f0);
            C2 v1 = cmul(u1, f1);
            #pragma unroll
            for (int q = 1; q <= 3; ++q) {
                C2 m[4]; build_m(m, U1[j][q], U2[j][q], (i >> q) & 1);
                const C2 n0 = cfma(v0, m[0], cmul(v1, m[2]));
                const C2 n1 = cfma(v0, m[1], cmul(v1, m[3]));
                v0 = n0; v1 = n1;
            }
            Ts[j][i] = make_float4(v0.r, v0.i, v1.r, v1.i);
        } else if (i < 32) {
            // T2[ii] = M4·M5·M6·M7  (2x2 chain)
            const int ii = i - 16;
            C2 A[4]; build_m(A, U1[j][4], U2[j][4], ii & 1);
            #pragma unroll
            for (int q = 5; q <= 7; ++q) {
                C2 B[4]; build_m(B, U1[j][q], U2[j][q], (ii >> (q - 4)) & 1);
                const C2 c00 = cfma(A[0], B[0], cmul(A[1], B[2]));
                const C2 c01 = cfma(A[0], B[1], cmul(A[1], B[3]));
                const C2 c10 = cfma(A[2], B[0], cmul(A[3], B[2]));
                const C2 c11 = cfma(A[2], B[1], cmul(A[3], B[3]));
                A[0] = c00; A[1] = c01; A[2] = c10; A[3] = c11;
            }
            Ts[j][16 + 2*ii]     = make_float4(A[0].r, A[0].i, A[1].r, A[1].i);
            Ts[j][16 + 2*ii + 1] = make_float4(A[2].r, A[2].i, A[3].r, A[3].i);
        } else if (i < 40) {
            // W[iw] = M8(c8)·M9(c9)·G(c10)   (col 2-vector chain)
            const int iw  = i - 32;
            const int c8  = iw & 1;
            const int c9  = (iw >> 1) & 1;
            const int c10 = iw >> 2;
            const C2 u0 = { U2[j][10][c10*4+0], U2[j][10][c10*4+1] };
            const C2 u1 = { U2[j][10][c10*4+2], U2[j][10][c10*4+3] };
            const C2 f0 = { U1[j][10][0], U1[j][10][1] };
            const C2 f1 = { U1[j][10][4], U1[j][10][5] };
            C2 g0 = cfma(u0, f0, cmul(u1, f1));   // G[zp=0]
            C2 g1 = cfma(u0, f1, cmul(u1, f0));   // G[zp=1]
            {
                C2 m[4]; build_m(m, U1[j][9], U2[j][9], c9);
                const C2 n0 = cfma(m[0], g0, cmul(m[1], g1));
                const C2 n1 = cfma(m[2], g0, cmul(m[3], g1));
                g0 = n0; g1 = n1;
            }
            {
                C2 m[4]; build_m(m, U1[j][8], U2[j][8], c8);
                const C2 n0 = cfma(m[0], g0, cmul(m[1], g1));
                const C2 n1 = cfma(m[2], g0, cmul(m[3], g1));
                g0 = n0; g1 = n1;
            }
            Ts[j][48 + iw] = make_float4(g0.r, g0.i, g1.r, g1.i);
        }
    }
    __syncthreads();

    // ---- Main: per-thread fold + 8 leaves, for each of the NB batches ----
    const int c  = (t ^ (t << 1)) & 255;   // graymap bits 0..7
    const int t7 = (t >> 7) & 1;

    #pragma unroll
    for (int j = 0; j < NB; ++j) {
        if (b0 + j >= batch) break;
        const float4 a  = Ts[j][c & 15];
        const float4 B0 = Ts[j][16 + 2*(c >> 4)];
        const float4 B1 = Ts[j][16 + 2*(c >> 4) + 1];
        const C2 a0 = { a.x, a.y }, a1 = { a.z, a.w };
        const C2 v20 = cfma(a0, { B0.x, B0.y }, cmul(a1, { B1.x, B1.y }));
        const C2 v21 = cfma(a0, { B0.z, B0.w }, cmul(a1, { B1.z, B1.w }));

        float* ob = out + (long long)(b0 + j) * SDIM + t;
        #pragma unroll
        for (int k = 0; k < 8; ++k) {
            const int cc = (((k ^ (k << 1)) & 7) ^ t7);   // warp-uniform
            const float4 w = Ts[j][48 + cc];
            const float val = v20.r*w.x - v20.i*w.y + v21.r*w.z - v21.i*w.w;
            ob[k << 8] = val;
        }
    }
}

extern "C" void kernel_launch(void* const* d_in, const int* in_sizes, int n_in,
                              void* d_out, int out_size)
{
    const float* theta     = (const float*)d_in[0];
    const int*   positions = (const int*)d_in[1];
    float*       out       = (float*)d_out;

    const int batch  = in_sizes[1];                 // 4096
    const int blocks = (batch + NB - 1) / NB;       // 1024
    pqc_kernel<<<blocks, NTHREADS>>>(theta, positions, out, batch);
}